// round 13
// baseline (speedup 1.0000x reference)
#include <cuda_runtime.h>
#include <cuda_bf16.h>

#define Hh 96
#define Ww 96
#define HW (Hh*Ww)
#define NS 8
#define NIMG (2*NS)
#define RPB 24                 // rows per block
#define NCHUNK (Hh/RPB)        // 4
#define NBLK (2*NS*NCHUNK)     // 64 blocks
#define NT 768                 // threads per block

// Cross-replay state. d_dirMax/d_count are zero at load; the LAST block of
// every launch resets them to zero after consuming them, so each graph replay
// starts clean with no init kernel and no init dependency.
__device__ int          d_dirMax[NIMG];
__device__ unsigned int d_count;

// ---------------------------------------------------------------------------
// Single launch, chip-filling. Block = (dir m, sample n, 24-row chunk rc).
//   dir 0: sources A\B vs target B;  dir 1: sources B\A vs target A.
// Each block independently rebuilds the TARGET mask's column bitsets
// (threshold -> ballot -> smem transpose; redundant across chunks but the
// 4.7MB of L2 broadcast reads cost ~0.5us chip-wide, vs ~5us for a second
// chip-wide launch). Then per pixel (3 px/thread, colbits loaded once per
// thread/column): O(1) column EDT via clz/ffs, early-exit integer row scan,
// block max reduce, atomicMax into the (n,m) slot. Last of 64 blocks combines
// the 16 slots with parallel atomic reads, writes the mean, resets state.
// ---------------------------------------------------------------------------
__global__ __launch_bounds__(NT, 2)
void k_hd(const float* __restrict__ predict,
          const float* __restrict__ target,
          float* __restrict__ out) {
    const int m  = blockIdx.x;
    const int n  = blockIdx.y;
    const int rc = blockIdx.z;
    const int t  = threadIdx.x;
    const int r  = t / Ww;             // 0..7
    const int j  = t - r * Ww;         // 0..95

    __shared__ unsigned       rb[HW / 32];     // target mask, row-major bits
    __shared__ unsigned       cb[Ww * 3];      // target mask, column bitsets
    __shared__ unsigned short g2[RPB][Ww];     // column-EDT^2 for our rows
    __shared__ float          red[NT / 32];

    const float* pa = predict + n * HW;
    const float* pb = target  + n * HW;
    const float* pt = (m == 0) ? pb : pa;      // target image for this dir

    // ---- S1: threshold target image -> row-major bitmask (ballot) ----------
    #pragma unroll
    for (int k = 0; k < HW / NT; k++) {
        int idx = k * NT + t;
        // jnp.round(x) > 0.5 for x in [0,1): true iff x > 0.5
        unsigned bw = __ballot_sync(0xffffffffu, pt[idx] > 0.5f);
        if ((t & 31) == 0) rb[idx >> 5] = bw;
    }
    __syncthreads();

    // ---- S2: transpose to column bitsets (9 warps, broadcast LDS) ----------
    if (t < Ww * 3) {
        int w  = t / Ww;               // 32-row chunk
        int jj = t - w * Ww;           // column
        unsigned cw = 0;
        #pragma unroll
        for (int rr = 0; rr < 32; rr++) {
            int i = w * 32 + rr;
            cw |= ((rb[i * 3 + (jj >> 5)] >> (jj & 31)) & 1u) << rr;
        }
        cb[jj * 3 + w] = cw;           // stride 3: conflict-free
    }
    __syncthreads();

    // ---- S3: column EDT (O(1) clz/ffs) + src membership, 3 px/thread -------
    unsigned c0 = cb[j * 3 + 0];
    unsigned c1 = cb[j * 3 + 1];
    unsigned c2 = cb[j * 3 + 2];

    bool srcv[3];
    #pragma unroll
    for (int k = 0; k < 3; k++) {
        int i = rc * RPB + r + 8 * k;
        int w = i >> 5, b = i & 31;
        unsigned wcur = (w == 0) ? c0 : ((w == 1) ? c1 : c2);
        unsigned wm1  = (w == 0) ? 0u : ((w == 1) ? c0 : c1);
        unsigned wm2  = (w == 2) ? c0 : 0u;
        unsigned wp1  = (w == 0) ? c1 : ((w == 1) ? c2 : 0u);
        unsigned wp2  = (w == 0) ? c2 : 0u;

        unsigned x = wcur & (0xffffffffu >> (31 - b));   // rows <= i
        int up;
        if (x)        up = b - (31 - __clz(x));
        else if (wm1) up = 32 + b - (31 - __clz(wm1));
        else if (wm2) up = 64 + b - (31 - __clz(wm2));
        else          up = 127;
        unsigned y = wcur & (0xffffffffu << b);          // rows >= i
        int down;
        if (y)        down = (__ffs(y) - 1) - b;
        else if (wp1) down = 32 - b + (__ffs(wp1) - 1);
        else if (wp2) down = 64 - b + (__ffs(wp2) - 1);
        else          down = 127;

        int g = min(up, down);
        g2[r + 8 * k][j] = (g >= Hh) ? (unsigned short)65535
                                     : (unsigned short)(g * g);

        bool av = pa[i * Ww + j] > 0.5f;   // coalesced: j contiguous
        bool bv = pb[i * Ww + j] > 0.5f;
        srcv[k] = (m == 0) ? (av && !bv) : (bv && !av);
    }
    __syncthreads();

    // ---- S4: early-exit outward row scan, per-thread max -------------------
    float l = 0.0f;
    #pragma unroll
    for (int k = 0; k < 3; k++) {
        if (srcv[k]) {
            const unsigned short* row = g2[r + 8 * k];
            int m2 = row[j];
            #pragma unroll 1
            for (int d = 1; d < Ww; d++) {
                int dd = d * d;
                if (dd >= m2) break;
                int lv = (j - d >= 0) ? (int)row[j - d] : 0x7FFFFF;
                int rv = (j + d < Ww) ? (int)row[j + d] : 0x7FFFFF;
                m2 = min(m2, min(lv, rv) + dd);
            }
            // m2 == 65535 exactly <=> target set empty (real dist^2 <= 18050)
            float v = (m2 >= 65535) ? 1e9f : sqrtf((float)m2) * (1.0f / 96.0f);
            l = fmaxf(l, v);
        }
    }

    // ---- S5: block reduce -> slot atomicMax -> last-block combine ----------
    #pragma unroll
    for (int off = 16; off > 0; off >>= 1)
        l = fmaxf(l, __shfl_xor_sync(0xffffffffu, l, off));
    if ((t & 31) == 0) red[t >> 5] = l;
    __syncthreads();

    if (t < 32) {
        float v = (t < NT / 32) ? red[t] : 0.0f;
        #pragma unroll
        for (int off = 16; off > 0; off >>= 1)
            v = fmaxf(v, __shfl_xor_sync(0xffffffffu, v, off));

        unsigned lastFlag = 0;
        if (t == 0) {
            // nonnegative floats: int-bit compare preserves order
            atomicMax(&d_dirMax[n * 2 + m], __float_as_int(v));
            __threadfence();
            lastFlag = (atomicAdd(&d_count, 1u) == (unsigned)(NBLK - 1)) ? 1u : 0u;
        }
        lastFlag = __shfl_sync(0xffffffffu, lastFlag, 0);
        if (lastFlag) {
            __threadfence();
            float pv = 0.0f;
            if (t < NIMG)
                pv = __int_as_float(atomicAdd(&d_dirMax[t], 0));  // 16 parallel
            if (t < NIMG)
                atomicExch(&d_dirMax[t], 0);       // reset for next replay
            float other   = __shfl_xor_sync(0xffffffffu, pv, 1);
            float pairmax = fmaxf(pv, other);      // max over (dir0, dir1)
            float contrib = ((t & 1) == 0 && t < NIMG) ? pairmax : 0.0f;
            #pragma unroll
            for (int off = 16; off > 0; off >>= 1)
                contrib += __shfl_xor_sync(0xffffffffu, contrib, off);
            if (t == 0) {
                out[0] = contrib * (1.0f / (float)NS);
                atomicExch(&d_count, 0u);          // reset for next replay
            }
        }
    }
}

extern "C" void kernel_launch(void* const* d_in, const int* in_sizes, int n_in,
                              void* d_out, int out_size) {
    const float* predict = (const float*)d_in[0];
    const float* target  = (const float*)d_in[1];
    float* out = (float*)d_out;

    dim3 grid(2, NS, NCHUNK);          // (direction, sample, row-chunk)
    k_hd<<<grid, NT>>>(predict, target, out);
}